// round 7
// baseline (speedup 1.0000x reference)
#include <cuda_runtime.h>
#include <cstdint>

#define ROWS 131072
#define COLS 256
#define NM   128
#define WPB  8                    // warps per block
#define RPW  8                    // rows per warp (looped)
#define THREADS (WPB * 32)

// Output = concat(masked_data, masked_indices, unmasked_data, unmasked_indices),
// each [ROWS, 128] row-major f32.
__global__ void __launch_bounds__(THREADS)
masker_kernel(const float* __restrict__ x,
              const int*   __restrict__ perm,
              float* __restrict__ out) {
    const int warp_id = threadIdx.x >> 5;
    const int lane    = threadIdx.x & 31;
    const int row0    = (blockIdx.x * WPB + warp_id) * RPW;

    __shared__ int   member[WPB][COLS];     // tag table (zeroed once)
    __shared__ float stage[WPB][3 * NM];    // [mi | ud | ui]

    int* mem = member[warp_id];
#pragma unroll
    for (int k = 0; k < 8; k++) mem[lane + 32 * k] = 0;
    __syncwarp();

    const int4*   P = reinterpret_cast<const int4*>(perm);  // 64 int4 / row
    const float4* X = reinterpret_cast<const float4*>(x);   // 64 float4 / row

    float* smi = stage[warp_id];
    float* sud = stage[warp_id] + NM;
    float* sui = stage[warp_id] + 2 * NM;

    const size_t seg = (size_t)ROWS * NM;

    // prefetch row 0
    size_t gb = (size_t)row0 * 64;
    int4   mh = P[gb + lane];
    float4 xa = X[gb + lane];
    float4 xb = X[gb + 32 + lane];

    for (int r = 0; r < RPW; r++) {
        const int row = row0 + r;
        int4   mh_c = mh;
        float4 xa_c = xa, xb_c = xb;

        // issue next row's loads before the dependent chain
        if (r + 1 < RPW) {
            const size_t nb = (size_t)(row + 1) * 64;
            mh = P[nb + lane];
            xa = X[nb + lane];
            xb = X[nb + 32 + lane];
        }

        // ---- membership via tag (values distinct -> no races) ----
        const int tag = r + 1;
        mem[mh_c.x] = tag;
        mem[mh_c.y] = tag;
        mem[mh_c.z] = tag;
        mem[mh_c.w] = tag;
        __syncwarp();

        unsigned mask[8];
#pragma unroll
        for (int w = 0; w < 8; w++)
            mask[w] = __ballot_sync(0xffffffffu, mem[32 * w + lane] == tag);
        __syncwarp();   // WAR: table reads done before next iter's writes

        int base[8];
        int acc = 0;
#pragma unroll
        for (int w = 0; w < 8; w++) { base[w] = acc; acc += __popc(mask[w]); }

        // lane-owned word select (compile-time SEL tree; w0 = lane>>3, w1 = w0+4)
        const bool hi = (lane & 16) != 0;
        const bool md = (lane & 8)  != 0;
        const unsigned mw0 = hi ? (md ? mask[3] : mask[2]) : (md ? mask[1] : mask[0]);
        const int      b0  = hi ? (md ? base[3] : base[2]) : (md ? base[1] : base[0]);
        const unsigned mw1 = hi ? (md ? mask[7] : mask[6]) : (md ? mask[5] : mask[4]);
        const int      b1  = hi ? (md ? base[7] : base[6]) : (md ? base[5] : base[4]);

        const float xv0[4] = {xa_c.x, xa_c.y, xa_c.z, xa_c.w};
        const float xv1[4] = {xb_c.x, xb_c.y, xb_c.z, xb_c.w};

        // ---- rank + scatter into stage, x straight from registers ----
#pragma unroll
        for (int j = 0; j < 4; j++) {
            const int c   = 4 * lane + j;
            const int bit = c & 31;
            const int mrank = b0 + __popc(mw0 & ((1u << bit) - 1u));
            if ((mw0 >> bit) & 1u) {
                smi[mrank] = (float)c;
            } else {
                const int urank = c - mrank;
                sud[urank] = xv0[j];
                sui[urank] = (float)c;
            }
        }
#pragma unroll
        for (int j = 0; j < 4; j++) {
            const int c   = 128 + 4 * lane + j;
            const int bit = c & 31;
            const int mrank = b1 + __popc(mw1 & ((1u << bit) - 1u));
            if ((mw1 >> bit) & 1u) {
                smi[mrank] = (float)c;
            } else {
                const int urank = c - mrank;
                sud[urank] = xv1[j];
                sui[urank] = (float)c;
            }
        }
        __syncwarp();

        // ---- coalesced write-out ----
        float4* o_md = reinterpret_cast<float4*>(out + (size_t)row * NM);
        float4* o_mi = reinterpret_cast<float4*>(out + seg     + (size_t)row * NM);
        float4* o_ud = reinterpret_cast<float4*>(out + 2 * seg + (size_t)row * NM);
        float4* o_ui = reinterpret_cast<float4*>(out + 3 * seg + (size_t)row * NM);

        o_md[lane] = make_float4(0.f, 0.f, 0.f, 0.f);
        o_mi[lane] = reinterpret_cast<float4*>(smi)[lane];
        o_ud[lane] = reinterpret_cast<float4*>(sud)[lane];
        o_ui[lane] = reinterpret_cast<float4*>(sui)[lane];
        __syncwarp();   // WAR: stage reads done before next iter's scatter
    }
}

extern "C" void kernel_launch(void* const* d_in, const int* in_sizes, int n_in,
                              void* d_out, int out_size) {
    const float* x    = (const float*)d_in[0];
    const int*   perm = (const int*)d_in[1];
    float* out = (float*)d_out;

    masker_kernel<<<ROWS / (WPB * RPW), THREADS>>>(x, perm, out);
}

// round 9
// speedup vs baseline: 1.0758x; 1.0758x over previous
#include <cuda_runtime.h>
#include <cstdint>

#define ROWS 131072
#define COLS 256
#define NM   128
#define WPB  8                    // warps per block (one row per warp)
#define THREADS (WPB * 32)

// Output = concat(masked_data, masked_indices, unmasked_data, unmasked_indices),
// each [ROWS, 128] row-major f32.
__global__ void __launch_bounds__(THREADS)
masker_kernel(const float* __restrict__ x,
              const int*   __restrict__ perm,
              float* __restrict__ out) {
    const int warp_id = threadIdx.x >> 5;
    const int lane    = threadIdx.x & 31;
    const int row     = blockIdx.x * WPB + warp_id;

    __shared__ float stage[WPB][3 * NM];    // [mi | ud | ui]

    // ---- global loads, front-batched ----
    const int4*   prow  = reinterpret_cast<const int4*>(perm + (size_t)row * COLS);
    const float4* xrow4 = reinterpret_cast<const float4*>(x + (size_t)row * COLS);
    int4   mh = prow[lane];         // masked half of permutation (first 128)
    float4 xa = xrow4[lane];        // x[4*lane .. 4*lane+3]
    float4 xb = xrow4[lane + 32];   // x[128+4*lane ..]

    // ---- build 256-bit membership bitmap in registers (no SMEM, no ballots) ----
    unsigned local[8] = {0, 0, 0, 0, 0, 0, 0, 0};
    {
        const int vs[4] = {mh.x, mh.y, mh.z, mh.w};
#pragma unroll
        for (int j = 0; j < 4; j++) {
            const int v = vs[j];
            const unsigned b = 1u << (v & 31);
            const int w = v >> 5;
#pragma unroll
            for (int ww = 0; ww < 8; ww++)
                local[ww] |= (w == ww) ? b : 0u;
        }
    }
    unsigned mask[8];
#pragma unroll
    for (int w = 0; w < 8; w++)
        mask[w] = __reduce_or_sync(0xffffffffu, local[w]);

    int base[8];                    // masked-count prefix over words
    int acc = 0;
#pragma unroll
    for (int w = 0; w < 8; w++) { base[w] = acc; acc += __popc(mask[w]); }

    float* smi = stage[warp_id];
    float* sud = stage[warp_id] + NM;
    float* sui = stage[warp_id] + 2 * NM;

    // lane-owned word select (compile-time SEL tree; w0 = lane>>3, w1 = w0+4)
    const bool hi = (lane & 16) != 0;
    const bool md = (lane & 8)  != 0;
    const unsigned mw0 = hi ? (md ? mask[3] : mask[2]) : (md ? mask[1] : mask[0]);
    const int      b0  = hi ? (md ? base[3] : base[2]) : (md ? base[1] : base[0]);
    const unsigned mw1 = hi ? (md ? mask[7] : mask[6]) : (md ? mask[5] : mask[4]);
    const int      b1  = hi ? (md ? base[7] : base[6]) : (md ? base[5] : base[4]);

    const float xv0[4] = {xa.x, xa.y, xa.z, xa.w};
    const float xv1[4] = {xb.x, xb.y, xb.z, xb.w};

    // ---- rank + scatter into stage, x straight from registers ----
#pragma unroll
    for (int j = 0; j < 4; j++) {
        const int c   = 4 * lane + j;
        const int bit = c & 31;
        const int mrank = b0 + __popc(mw0 & ((1u << bit) - 1u));
        if ((mw0 >> bit) & 1u) {
            smi[mrank] = (float)c;
        } else {
            const int urank = c - mrank;
            sud[urank] = xv0[j];
            sui[urank] = (float)c;
        }
    }
#pragma unroll
    for (int j = 0; j < 4; j++) {
        const int c   = 128 + 4 * lane + j;
        const int bit = c & 31;
        const int mrank = b1 + __popc(mw1 & ((1u << bit) - 1u));
        if ((mw1 >> bit) & 1u) {
            smi[mrank] = (float)c;
        } else {
            const int urank = c - mrank;
            sud[urank] = xv1[j];
            sui[urank] = (float)c;
        }
    }
    __syncwarp();

    // ---- coalesced write-out ----
    const size_t seg = (size_t)ROWS * NM;
    float4* o_md = reinterpret_cast<float4*>(out + (size_t)row * NM);
    float4* o_mi = reinterpret_cast<float4*>(out + seg     + (size_t)row * NM);
    float4* o_ud = reinterpret_cast<float4*>(out + 2 * seg + (size_t)row * NM);
    float4* o_ui = reinterpret_cast<float4*>(out + 3 * seg + (size_t)row * NM);

    o_md[lane] = make_float4(0.f, 0.f, 0.f, 0.f);
    o_mi[lane] = reinterpret_cast<float4*>(smi)[lane];
    o_ud[lane] = reinterpret_cast<float4*>(sud)[lane];
    o_ui[lane] = reinterpret_cast<float4*>(sui)[lane];
}

extern "C" void kernel_launch(void* const* d_in, const int* in_sizes, int n_in,
                              void* d_out, int out_size) {
    const float* x    = (const float*)d_in[0];
    const int*   perm = (const int*)d_in[1];
    float* out = (float*)d_out;

    masker_kernel<<<ROWS / WPB, THREADS>>>(x, perm, out);
}